// round 2
// baseline (speedup 1.0000x reference)
#include <cuda_runtime.h>
#include <math.h>

// ---------------- problem constants ----------------
#define NB   16
#define HIN  512
#define WIN  512
#define HS   256
#define WS   256
#define HF   128
#define WF   128
#define CF   64
#define CH   704          // concat channels
#define PP   23
#define NPIX (PP*PP)      // 529
#define NROI 176          // 112 (7 boxes on f) + 4*16

// ---------------- scratch buffers (device globals; no allocation) ----------------
__device__ float g_stem[(size_t)NB*64*HS*WS];       // 268 MB
__device__ float g_f  [(size_t)NB*CF*HF*WF];
__device__ float g_xt1[(size_t)NB*CF*HF*WF];
__device__ float g_xt2[(size_t)NB*CF*HF*WF];
__device__ float g_h  [(size_t)NB*CH*NPIX];
__device__ float g_c1 [(size_t)NB*64*21*21];
__device__ float g_pool[(size_t)NB*64*10*10];
__device__ float g_c2 [(size_t)NB*32*8*8];
__device__ float g_stats_a[64*16*2];
__device__ float g_stats_b[64*16*2];
__device__ float g_bn_stem[64*2];
__device__ float g_bn_c1[64*2];

// ==================================================================
// Kernel 1: stem conv 7x7 stride2 pad3, input NHWC (16,512,512,3) -> (16,64,256,256)
// tile: 32 (x) x 16 (y) outputs, block (32,4), each thread 4 rows x 8 oc
// ==================================================================
__global__ __launch_bounds__(128) void k_stem(const float* __restrict__ x,
                                              const float* __restrict__ w) {
    __shared__ float s_in[3*37*72];   // patch [c][37][pitch 72]
    __shared__ float s_w[1176];       // 8 oc * 147
    const int tx = threadIdx.x, ty = threadIdx.y;
    const int tid = ty*32 + tx;
    const int bx = blockIdx.x, by = blockIdx.y, b = blockIdx.z;
    const int ox  = bx*32 + tx;
    const int iy0 = by*32 - 3;
    const int ix0 = bx*64 - 3;

    for (int i = tid; i < 3*37*69; i += 128) {
        int c  = i / (37*69);
        int rr = i - c*(37*69);
        int py = rr / 69, px = rr - py*69;
        int ih = iy0 + py, iw = ix0 + px;
        float v = 0.f;
        if (ih >= 0 && ih < 512 && iw >= 0 && iw < 512)
            v = x[((size_t)(b*512 + ih)*512 + iw)*3 + c];
        s_in[c*(37*72) + py*72 + px] = v;
    }

    for (int ocb = 0; ocb < 8; ocb++) {
        __syncthreads();
        for (int i = tid; i < 1176; i += 128) s_w[i] = w[ocb*1176 + i];
        __syncthreads();

        float acc[4][8];
        #pragma unroll
        for (int r = 0; r < 4; r++)
            #pragma unroll
            for (int o = 0; o < 8; o++) acc[r][o] = 0.f;

        for (int c = 0; c < 3; c++) {
            for (int ky = 0; ky < 7; ky++) {
                const float* row0 = &s_in[c*2664 + (2*ty      + ky)*72 + 2*tx];
                const float* row1 = &s_in[c*2664 + (2*ty + 8  + ky)*72 + 2*tx];
                const float* row2 = &s_in[c*2664 + (2*ty + 16 + ky)*72 + 2*tx];
                const float* row3 = &s_in[c*2664 + (2*ty + 24 + ky)*72 + 2*tx];
                const float* wp   = &s_w[c*49 + ky*7];
                #pragma unroll
                for (int kx = 0; kx < 7; kx++) {
                    float i0 = row0[kx], i1 = row1[kx], i2 = row2[kx], i3 = row3[kx];
                    #pragma unroll
                    for (int o = 0; o < 8; o++) {
                        float wv = wp[o*147 + kx];
                        acc[0][o] += i0*wv; acc[1][o] += i1*wv;
                        acc[2][o] += i2*wv; acc[3][o] += i3*wv;
                    }
                }
            }
        }
        #pragma unroll
        for (int r = 0; r < 4; r++) {
            int oy = by*16 + ty + 4*r;
            #pragma unroll
            for (int o = 0; o < 8; o++) {
                int oc = ocb*8 + o;
                g_stem[((size_t)(b*64 + oc)*256 + oy)*256 + ox] = acc[r][o];
            }
        }
    }
}

// ==================================================================
// Kernel 2: per-(b,oc) partial sum / sumsq (deterministic tree reduce)
// grid (b=16, oc=64), 256 threads
// ==================================================================
__global__ void k_stats(const float* __restrict__ src, float* __restrict__ partial,
                        int planeN) {
    int b = blockIdx.x, oc = blockIdx.y;
    const float* p = src + ((size_t)b*64 + oc)*(size_t)planeN;
    float s = 0.f, q = 0.f;
    for (int i = threadIdx.x; i < planeN; i += blockDim.x) {
        float v = p[i]; s += v; q += v*v;
    }
    __shared__ float ss[256], sq[256];
    ss[threadIdx.x] = s; sq[threadIdx.x] = q;
    __syncthreads();
    for (int st = 128; st > 0; st >>= 1) {
        if (threadIdx.x < st) {
            ss[threadIdx.x] += ss[threadIdx.x + st];
            sq[threadIdx.x] += sq[threadIdx.x + st];
        }
        __syncthreads();
    }
    if (threadIdx.x == 0) {
        partial[(oc*16 + b)*2 + 0] = ss[0];
        partial[(oc*16 + b)*2 + 1] = sq[0];
    }
}

__global__ void k_stats_fin(const float* __restrict__ partial,
                            const float* __restrict__ g, const float* __restrict__ bta,
                            float* __restrict__ bn, float invN) {
    int oc = threadIdx.x;  // 64 threads
    float s = 0.f, q = 0.f;
    for (int b = 0; b < 16; b++) {
        s += partial[(oc*16 + b)*2 + 0];
        q += partial[(oc*16 + b)*2 + 1];
    }
    float m  = s*invN;
    float v  = q*invN - m*m;
    float sc = g[oc] * rsqrtf(v + 1e-5f);
    bn[oc*2 + 0] = sc;
    bn[oc*2 + 1] = bta[oc] - m*sc;
}

// ==================================================================
// Kernel 3: BN + ReLU + maxpool 3x3 s2 p1 : (16,64,256,256) -> (16,64,128,128)
// ==================================================================
__global__ void k_bnpool3() {
    int idx = blockIdx.x*256 + threadIdx.x;
    if (idx >= NB*CF*HF*WF) return;
    int xo = idx & 127;
    int yo = (idx >> 7) & 127;
    int cb = idx >> 14;         // b*64+c
    int c  = cb & 63;
    float sc = g_bn_stem[c*2], bi = g_bn_stem[c*2 + 1];
    const float* p = g_stem + (size_t)cb*65536;
    float m = -3.402823466e+38f;
    #pragma unroll
    for (int ky = 0; ky < 3; ky++) {
        int iy = 2*yo - 1 + ky;
        if (iy < 0 || iy > 255) continue;
        #pragma unroll
        for (int kx = 0; kx < 3; kx++) {
            int ix = 2*xo - 1 + kx;
            if (ix < 0 || ix > 255) continue;
            float v = sc*p[iy*256 + ix] + bi;
            m = fmaxf(m, v);
        }
    }
    g_f[idx] = fmaxf(m, 0.f);
}

// ==================================================================
// Kernel 4: grid_sample with +/-5 degree rotation : g_f -> g_xt1, g_xt2
// ==================================================================
__device__ __forceinline__ float gs_fetch(const float* pl, int y, int x) {
    if (x < 0 || x > 127 || y < 0 || y > 127) return 0.f;
    return pl[y*128 + x];
}

__global__ void k_gsample() {
    int idx = blockIdx.x*256 + threadIdx.x;
    if (idx >= 2*NB*CF*HF*WF) return;
    int which = idx >> 24;            // 16*64*128*128 = 2^24
    int rr = idx & 0xFFFFFF;
    int xo = rr & 127;
    int yo = (rr >> 7) & 127;
    int cb = rr >> 14;
    const float C5 = 0.99619469809174553f;
    const float S5 = 0.08715574274765817f;
    float gx = (float)(2*xo + 1) * (1.0f/128.0f) - 1.0f;
    float gy = (float)(2*yo + 1) * (1.0f/128.0f) - 1.0f;
    float g0, g1;
    if (which == 0) { g0 =  C5*gx + S5*gy; g1 = -S5*gx + C5*gy; }   // a=-5deg
    else            { g0 =  C5*gx - S5*gy; g1 =  S5*gx + C5*gy; }   // a=+5deg
    float ixf = ((g0 + 1.f)*128.f - 1.f)*0.5f;
    float iyf = ((g1 + 1.f)*128.f - 1.f)*0.5f;
    float x0f = floorf(ixf), y0f = floorf(iyf);
    int   x0 = (int)x0f,   y0 = (int)y0f;
    float lx = ixf - x0f, ly = iyf - y0f;
    float hx = 1.f - lx,  hy = 1.f - ly;
    const float* pl = g_f + (size_t)cb*16384;
    float v = gs_fetch(pl, y0,   x0  )*hx*hy
            + gs_fetch(pl, y0+1, x0  )*hx*ly
            + gs_fetch(pl, y0,   x0+1)*lx*hy
            + gs_fetch(pl, y0+1, x0+1)*lx*ly;
    (which ? g_xt2 : g_xt1)[rr] = v;
}

// ==================================================================
// Kernel 5: ROI align (176 rois) writing directly into concat buffer g_h
// ==================================================================
__global__ void k_roialign(const float* __restrict__ box) {
    int idx = blockIdx.x*256 + threadIdx.x;
    if (idx >= NROI*64*NPIX) return;
    int p = idx % NPIX;
    int t = idx / NPIX;
    int c = t & 63;
    int r = t >> 6;

    const float* src; int bb, k, och;
    if (r < 112) {                       // f7: roi r = k*16 + b on f
        k = r >> 4; bb = r & 15; src = g_f; och = k*64 + c;
    } else {
        int u = r - 112; int grp = u >> 4; bb = u & 15; k = grp & 1;
        src = (grp < 2) ? g_xt1 : g_xt2;
        och = 448 + grp*64 + c;
    }
    const float* bp = box + bb*28 + k*4;
    float x1 = bp[0]*0.25f, y1v = bp[1]*0.25f, x2 = bp[2]*0.25f, y2 = bp[3]*0.25f;
    float bw = fmaxf(x2 - x1, 1.0f) * (1.0f/23.0f);
    float bh = fmaxf(y2 - y1v, 1.0f) * (1.0f/23.0f);
    int py = p / 23, px = p - py*23;
    const float* plane = src + ((size_t)bb*64 + c)*16384;

    float acc = 0.f;
    #pragma unroll
    for (int dy = 0; dy < 2; dy++) {
        float posy = (float)py + 0.25f + 0.5f*(float)dy;
        float yv = y1v + posy*bh;
        bool ey = (yv < -1.0f) || (yv > 128.0f);
        float yc  = fminf(fmaxf(yv, 0.f), 127.f);
        float y0f = floorf(yc);
        int y0 = (int)y0f; int y1i = min(y0 + 1, 127);
        float ly = yc - y0f, hy = 1.f - ly;
        #pragma unroll
        for (int dx = 0; dx < 2; dx++) {
            float posx = (float)px + 0.25f + 0.5f*(float)dx;
            float xv = x1 + posx*bw;
            bool ex = (xv < -1.0f) || (xv > 128.0f);
            float xc  = fminf(fmaxf(xv, 0.f), 127.f);
            float x0f = floorf(xc);
            int x0 = (int)x0f; int x1i = min(x0 + 1, 127);
            float lx = xc - x0f, hx = 1.f - lx;
            float v = plane[y0*128 + x0 ]*hy*hx + plane[y0*128 + x1i ]*hy*lx
                    + plane[y1i*128 + x0]*ly*hx + plane[y1i*128 + x1i]*ly*lx;
            if (ey || ex) v = 0.f;
            acc += v;
        }
    }
    g_h[((size_t)bb*CH + och)*NPIX + p] = acc * 0.25f;
}

// ==================================================================
// Kernel 6: conv1 704->64 3x3 valid : (16,704,23,23) -> (16,64,21,21)
// grid (b=16, ocb=8), 224 threads; each thread 2 px * 8 oc
// ==================================================================
__global__ __launch_bounds__(224) void k_conv1(const float* __restrict__ w,
                                               const float* __restrict__ bias) {
    __shared__ float s_in[16*529];   // 16 input channels x 23x23
    __shared__ float s_w[1152];      // 8 oc x 16 ic x 9
    const int b = blockIdx.x, ocb = blockIdx.y;
    const int tid = threadIdx.x;
    const int p0 = tid, p1 = tid + 224;
    const int py0 = p0/21, px0 = p0 - py0*21;
    const int py1 = p1/21, px1 = p1 - py1*21;
    const bool v1 = (p1 < 441);

    float a0[8], a1[8];
    #pragma unroll
    for (int o = 0; o < 8; o++) { a0[o] = 0.f; a1[o] = 0.f; }

    for (int icb = 0; icb < 44; icb++) {
        __syncthreads();
        for (int i = tid; i < 16*529; i += 224) {
            int ci = i / 529, pp = i - ci*529;
            s_in[i] = g_h[((size_t)b*CH + icb*16 + ci)*NPIX + pp];
        }
        for (int i = tid; i < 1152; i += 224) {
            int ol = i / 144, rr = i - ol*144;
            s_w[i] = w[(size_t)(ocb*8 + ol)*6336 + icb*144 + rr];
        }
        __syncthreads();

        for (int ci = 0; ci < 16; ci++) {
            const float* ip = s_in + ci*529;
            const float* wp = s_w + ci*9;
            #pragma unroll
            for (int ky = 0; ky < 3; ky++) {
                #pragma unroll
                for (int kx = 0; kx < 3; kx++) {
                    float i0 = ip[(py0 + ky)*23 + px0 + kx];
                    float i1 = ip[(py1 + ky)*23 + px1 + kx];
                    #pragma unroll
                    for (int o = 0; o < 8; o++) {
                        float wv = wp[o*144 + ky*3 + kx];
                        a0[o] += i0*wv; a1[o] += i1*wv;
                    }
                }
            }
        }
    }
    #pragma unroll
    for (int o = 0; o < 8; o++) {
        int oc = ocb*8 + o;
        float bz = bias[oc];
        g_c1[((size_t)b*64 + oc)*441 + p0] = a0[o] + bz;
        if (v1) g_c1[((size_t)b*64 + oc)*441 + p1] = a1[o] + bz;
    }
}

// ==================================================================
// Kernel 7: BN + ReLU + maxpool 2x2 s2 : (16,64,21,21) -> (16,64,10,10)
// ==================================================================
__global__ void k_bnpool2() {
    int idx = blockIdx.x*256 + threadIdx.x;
    if (idx >= NB*64*100) return;
    int xo = idx % 10;
    int yo = (idx / 10) % 10;
    int cb = idx / 100;
    int c  = cb & 63;
    float sc = g_bn_c1[c*2], bi = g_bn_c1[c*2 + 1];
    const float* p = g_c1 + (size_t)cb*441;
    float m = -3.402823466e+38f;
    #pragma unroll
    for (int dy = 0; dy < 2; dy++)
        #pragma unroll
        for (int dx = 0; dx < 2; dx++) {
            float v = sc*p[(2*yo + dy)*21 + 2*xo + dx] + bi;
            m = fmaxf(m, v);
        }
    g_pool[idx] = fmaxf(m, 0.f);
}

// ==================================================================
// Kernel 8: conv2 64->32 3x3 valid + ReLU : (16,64,10,10) -> (16,32,8,8)
// ==================================================================
__global__ void k_conv2(const float* __restrict__ w, const float* __restrict__ bias) {
    int idx = blockIdx.x*256 + threadIdx.x;
    if (idx >= NB*32*64) return;
    int p  = idx & 63;
    int oc = (idx >> 6) & 31;
    int b  = idx >> 11;
    int py = p >> 3, px = p & 7;
    float a = bias[oc];
    for (int ic = 0; ic < 64; ic++) {
        const float* ip = g_pool + ((size_t)b*64 + ic)*100;
        const float* wp = w + (size_t)oc*576 + ic*9;
        #pragma unroll
        for (int ky = 0; ky < 3; ky++)
            #pragma unroll
            for (int kx = 0; kx < 3; kx++)
                a += ip[(py + ky)*10 + px + kx] * wp[ky*3 + kx];
    }
    g_c2[idx] = fmaxf(a, 0.f);
}

// ==================================================================
// Kernel 9: fc1(2048->128)+ReLU then head(128->12)+tanh
// ==================================================================
__global__ void k_fc(const float* __restrict__ fc1w, const float* __restrict__ fc1b,
                     const float* __restrict__ hw,   const float* __restrict__ hb,
                     float* __restrict__ out) {
    __shared__ float sh[128];
    int b = blockIdx.x, j = threadIdx.x;
    const float* xin = g_c2 + (size_t)b*2048;
    const float* wr  = fc1w + (size_t)j*2048;
    float s = fc1b[j];
    for (int k = 0; k < 2048; k++) s += xin[k]*wr[k];
    sh[j] = fmaxf(s, 0.f);
    __syncthreads();
    if (j < 12) {
        float s2 = hb[j];
        const float* hr = hw + j*128;
        for (int k = 0; k < 128; k++) s2 += sh[k]*hr[k];
        out[b*12 + j] = tanhf(s2);
    }
}

// ==================================================================
extern "C" void kernel_launch(void* const* d_in, const int* in_sizes, int n_in,
                              void* d_out, int out_size) {
    const float* x       = (const float*)d_in[0];
    const float* box     = (const float*)d_in[1];
    const float* stem_w  = (const float*)d_in[2];
    const float* stem_g  = (const float*)d_in[3];
    const float* stem_b  = (const float*)d_in[4];
    const float* conv1_w = (const float*)d_in[5];
    const float* conv1_b = (const float*)d_in[6];
    const float* bn1_g   = (const float*)d_in[7];
    const float* bn1_b   = (const float*)d_in[8];
    const float* conv2_w = (const float*)d_in[9];
    const float* conv2_b = (const float*)d_in[10];
    const float* fc1_w   = (const float*)d_in[11];
    const float* fc1_b   = (const float*)d_in[12];
    const float* head_w  = (const float*)d_in[13];
    const float* head_b  = (const float*)d_in[14];
    float* out = (float*)d_out;

    float *p_stem, *p_stats_a, *p_stats_b, *p_bn_stem, *p_bn_c1, *p_c1;
    cudaGetSymbolAddress((void**)&p_stem,    g_stem);
    cudaGetSymbolAddress((void**)&p_stats_a, g_stats_a);
    cudaGetSymbolAddress((void**)&p_stats_b, g_stats_b);
    cudaGetSymbolAddress((void**)&p_bn_stem, g_bn_stem);
    cudaGetSymbolAddress((void**)&p_bn_c1,   g_bn_c1);
    cudaGetSymbolAddress((void**)&p_c1,      g_c1);

    // 1. stem conv
    k_stem<<<dim3(8,16,16), dim3(32,4)>>>(x, stem_w);
    // 2. stem BN stats
    k_stats<<<dim3(16,64), 256>>>(p_stem, p_stats_a, 65536);
    k_stats_fin<<<1,64>>>(p_stats_a, stem_g, stem_b, p_bn_stem,
                          1.0f/(16.0f*65536.0f));
    // 3. BN+ReLU+maxpool3
    k_bnpool3<<<(NB*CF*HF*WF)/256, 256>>>();
    // 4. grid sample (both thetas)
    k_gsample<<<(2*NB*CF*HF*WF)/256, 256>>>();
    // 5. roi align -> concat buffer
    k_roialign<<<(NROI*64*NPIX + 255)/256, 256>>>(box);
    // 6. conv1
    k_conv1<<<dim3(16,8), 224>>>(conv1_w, conv1_b);
    // 7. conv1 BN stats
    k_stats<<<dim3(16,64), 256>>>(p_c1, p_stats_b, 441);
    k_stats_fin<<<1,64>>>(p_stats_b, bn1_g, bn1_b, p_bn_c1, 1.0f/7056.0f);
    // 8. BN+ReLU+maxpool2
    k_bnpool2<<<(NB*64*100 + 255)/256, 256>>>();
    // 9. conv2+relu
    k_conv2<<<(NB*32*64 + 255)/256, 256>>>(conv2_w, conv2_b);
    // 10. fc + head
    k_fc<<<16, 128>>>(fc1_w, fc1_b, head_w, head_b, out);
}